// round 11
// baseline (speedup 1.0000x reference)
#include <cuda_runtime.h>
#include <cuda_fp16.h>

#define NN 100000
#define NE 1000000
#define NG 512
#define HID 64
#define EDIM 32
#define ZW 160
#define NLAYERS 4

typedef unsigned long long ull;
typedef unsigned int uint;

// ---------------- scratch ----------------
__device__ float d_x[NN * HID];
__device__ uint  d_nd[NN * 64];       // dst terms: half2(Af), half2(As) (bias incl.)
__device__ uint  d_ns[NN * 64];       // src terms: half2(Bf), half2(Bs)
__device__ float d_agg[NN * HID];
__device__ double d_sum1[NLAYERS][64];
__device__ double d_sumsq1[NLAYERS][64];
__device__ double d_sum2[NLAYERS][64];
__device__ double d_sumsq2[NLAYERS][64];
__device__ float d_pool[NG * HID];
__device__ float d_cnt[NG];

// ---------------- helpers ----------------
__device__ __forceinline__ float sigmoidf_(float x) {
    return __fdividef(1.0f, 1.0f + __expf(-x));
}
__device__ __forceinline__ float sigmoid_tanh_(float x) {
    float t;
    asm("tanh.approx.f32 %0, %1;" : "=f"(t) : "f"(x * 0.5f));
    return fmaf(0.5f, t, 0.5f);
}
__device__ __forceinline__ float softplusf_(float x) {
    float e = __expf(-fabsf(x));
    return fmaxf(x, 0.0f) + __logf(1.0f + e);
}
__device__ __forceinline__ uint h2u(__half2 h) { return *(uint*)&h; }

// mma.sync m16n8k16 f16 inputs, f32 accumulate
__device__ __forceinline__ void mma16816(float c[4], const uint a[4], const uint b[2]) {
    asm volatile(
        "mma.sync.aligned.m16n8k16.row.col.f32.f16.f16.f32 "
        "{%0,%1,%2,%3}, {%4,%5,%6,%7}, {%8,%9}, {%0,%1,%2,%3};"
        : "+f"(c[0]), "+f"(c[1]), "+f"(c[2]), "+f"(c[3])
        : "r"(a[0]), "r"(a[1]), "r"(a[2]), "r"(a[3]), "r"(b[0]), "r"(b[1]));
}

// ---------------- kernels ----------------

__global__ void k_gather(const int* __restrict__ z, const float* __restrict__ emb) {
    int i = blockIdx.x * blockDim.x + threadIdx.x;
    if (i < NN * HID) {
        int n = i >> 6, c = i & 63;
        d_x[i] = emb[z[n] * HID + c];
        d_agg[i] = 0.f;
    }
    if (i < NLAYERS * 64) {
        int l = i >> 6, c = i & 63;
        d_sum1[l][c] = 0.0; d_sumsq1[l][c] = 0.0;
        d_sum2[l][c] = 0.0; d_sumsq2[l][c] = 0.0;
    }
}

// Tensor-core node pre-GEMM (round-10 version).
__global__ __launch_bounds__(256) void k_node_pre(
    const float* __restrict__ Wf, const float* __restrict__ bf,
    const float* __restrict__ Ws, const float* __restrict__ bs,
    const float* __restrict__ go, const float* __restrict__ bo,
    int prev_layer)
{
    __shared__ __half sxh[64][72];

    int tid = threadIdx.x;
    int warp = tid >> 5;
    int lane = tid & 31;
    int gid = lane >> 2;
    int tig = lane & 3;

    float mn[4], rsg[4], bb[4];
    if (prev_layer >= 0) {
        int q = tid & 15;
#pragma unroll
        for (int j = 0; j < 4; j++) {
            int c = 4 * q + j;
            double mean = d_sum2[prev_layer][c] * (1.0 / NN);
            double var  = d_sumsq2[prev_layer][c] * (1.0 / NN) - mean * mean;
            float rs = (float)rsqrt(var + 1e-5);
            mn[j] = (float)mean; rsg[j] = rs * go[c]; bb[j] = bo[c];
        }
    }

    int m = warp >> 1;
    int chb = (warp & 1) * 32;
    const float* Wsrc;
    const float* bias = nullptr;
    uint* outp;
    int slot;
    if (m == 0)      { Wsrc = Wf;            bias = bf; outp = d_nd; slot = 0; }
    else if (m == 1) { Wsrc = Wf + 64 * HID;            outp = d_ns; slot = 0; }
    else if (m == 2) { Wsrc = Ws;            bias = bs; outp = d_nd; slot = 1; }
    else             { Wsrc = Ws + 64 * HID;            outp = d_ns; slot = 1; }

    uint b[4][4][2];
#pragma unroll
    for (int nt = 0; nt < 4; nt++) {
#pragma unroll
        for (int kt = 0; kt < 4; kt++) {
            int ch = chb + nt * 8 + gid;
            int k0 = kt * 16 + tig * 2;
            b[nt][kt][0] = h2u(__floats2half2_rn(Wsrc[k0 * HID + ch],
                                                 Wsrc[(k0 + 1) * HID + ch]));
            b[nt][kt][1] = h2u(__floats2half2_rn(Wsrc[(k0 + 8) * HID + ch],
                                                 Wsrc[(k0 + 9) * HID + ch]));
        }
    }
    float bi[4][2];
#pragma unroll
    for (int nt = 0; nt < 4; nt++) {
        int ch = chb + nt * 8 + tig * 2;
        bi[nt][0] = bias ? bias[ch]     : 0.f;
        bi[nt][1] = bias ? bias[ch + 1] : 0.f;
    }

    for (int nb = blockIdx.x * 64; nb < NN; nb += gridDim.x * 64) {
        int nmax = NN - nb; if (nmax > 64) nmax = 64;

        {
            const float4* x4 = (const float4*)(d_x + (ull)nb * HID);
            float4* a4 = (float4*)(d_agg + (ull)nb * HID);
            float4* xw4 = (float4*)(d_x + (ull)nb * HID);
            for (int i = tid; i < nmax * 16; i += 256) {
                int n = i >> 4, q = i & 15;
                float4 v;
                if (prev_layer >= 0) {
                    float4 a = a4[i];
                    v.x = softplusf_((a.x - mn[0]) * rsg[0] + bb[0]);
                    v.y = softplusf_((a.y - mn[1]) * rsg[1] + bb[1]);
                    v.z = softplusf_((a.z - mn[2]) * rsg[2] + bb[2]);
                    v.w = softplusf_((a.w - mn[3]) * rsg[3] + bb[3]);
                    xw4[i] = v;
                    a4[i] = make_float4(0.f, 0.f, 0.f, 0.f);
                } else {
                    v = x4[i];
                }
                __half2 h0 = __floats2half2_rn(v.x, v.y);
                __half2 h1 = __floats2half2_rn(v.z, v.w);
                *(uint2*)&sxh[n][4 * q] = make_uint2(h2u(h0), h2u(h1));
            }
        }
        __syncthreads();

#pragma unroll
        for (int mt = 0; mt < 4; mt++) {
            float c[4][4];
#pragma unroll
            for (int nt = 0; nt < 4; nt++) {
                c[nt][0] = bi[nt][0]; c[nt][1] = bi[nt][1];
                c[nt][2] = bi[nt][0]; c[nt][3] = bi[nt][1];
            }
#pragma unroll
            for (int kt = 0; kt < 4; kt++) {
                uint a[4];
                const __half* p = &sxh[mt * 16 + gid][kt * 16 + tig * 2];
                a[0] = *(const uint*)p;
                a[1] = *(const uint*)(p + 8 * 72);
                a[2] = *(const uint*)(p + 8);
                a[3] = *(const uint*)(p + 8 * 72 + 8);
#pragma unroll
                for (int nt = 0; nt < 4; nt++)
                    mma16816(c[nt], a, b[nt][kt]);
            }
            int r0 = nb + mt * 16 + gid;
            int r1 = r0 + 8;
#pragma unroll
            for (int nt = 0; nt < 4; nt++) {
                int ch = chb + nt * 8 + tig * 2;
                if (r0 < NN) outp[(ull)r0 * 64 + ch + slot] = h2u(__floats2half2_rn(c[nt][0], c[nt][1]));
                if (r1 < NN) outp[(ull)r1 * 64 + ch + slot] = h2u(__floats2half2_rn(c[nt][2], c[nt][3]));
            }
        }
        __syncthreads();
    }
}

__global__ void k_zero_pool() {
    int i = blockIdx.x * blockDim.x + threadIdx.x;
    if (i < NG * HID) d_pool[i] = 0.f;
    if (i < NG) d_cnt[i] = 0.f;
}

// Fused edge kernel: HMMA GEMM + v4-vectorized apply (16 lanes/edge, 4 ch/lane).
__global__ __launch_bounds__(128) void k_edge_fused(
    const int* __restrict__ ei, const float* __restrict__ ea,
    const float* __restrict__ Wf, const float* __restrict__ Ws)
{
    __shared__ __half sea_h[32][40];
    __shared__ float sE[32][132];
    __shared__ int sidx[64];

    int tid = threadIdx.x;
    int warp = tid >> 5;
    int lane = tid & 31;
    int gid = lane >> 2;
    int tig = lane & 3;
    int half = lane >> 4;     // apply: which edge of the pair
    int q = lane & 15;        // apply: channel group (4 ch)

    const float* W = (warp >> 1) ? Ws : Wf;
    int chb = (warp & 1) * 32;
    int outbase = (warp >> 1) * 64 + chb;

    uint b[4][2][2];
#pragma unroll
    for (int nt = 0; nt < 4; nt++) {
#pragma unroll
        for (int kt = 0; kt < 2; kt++) {
            int ch = chb + nt * 8 + gid;
            int k0 = kt * 16 + tig * 2;
            b[nt][kt][0] = h2u(__floats2half2_rn(W[(128 + k0)     * HID + ch],
                                                 W[(128 + k0 + 1) * HID + ch]));
            b[nt][kt][1] = h2u(__floats2half2_rn(W[(128 + k0 + 8) * HID + ch],
                                                 W[(128 + k0 + 9) * HID + ch]));
        }
    }

    const int stride = gridDim.x * 32;
    int base = blockIdx.x * 32;

    if (base < NE) {
        if (tid < 32)      sidx[tid] = ei[base + tid];
        else if (tid < 64) sidx[tid] = ei[NE + base + tid - 32];
        const float4* s4 = (const float4*)(ea + (ull)base * EDIM);
#pragma unroll
        for (int u = 0; u < 2; u++) {
            int i = tid + u * 128;
            float4 v = __ldcs(s4 + i);
            int e = i >> 3, k4 = (i & 7) * 4;
            __half2 h0 = __floats2half2_rn(v.x, v.y);
            __half2 h1 = __floats2half2_rn(v.z, v.w);
            *(uint2*)&sea_h[e][k4] = make_uint2(h2u(h0), h2u(h1));
        }
    }
    __syncthreads();

    for (; base < NE; base += stride) {
        int nb = base + stride;
        int lb = (nb < NE) ? nb : 0;

        // this lane's 4 apply edges (pairs t*2 + half)
        int srcs[4], dsts[4];
#pragma unroll
        for (int t = 0; t < 4; t++) {
            int e = warp * 8 + t * 2 + half;
            srcs[t] = sidx[e];
            dsts[t] = sidx[32 + e];
        }

        const float4* s4 = (const float4*)(ea + (ull)lb * EDIM);
        float4 n0 = __ldcs(s4 + tid);
        float4 n1 = __ldcs(s4 + tid + 128);
        int nidx = 0;
        if (tid < 32)      nidx = ei[lb + tid];
        else if (tid < 64) nidx = ei[NE + lb + tid - 32];

        // ---- GEMM: 16 HMMA per warp ----
        float c[2][4][4];
#pragma unroll
        for (int mt = 0; mt < 2; mt++)
#pragma unroll
            for (int nt = 0; nt < 4; nt++)
#pragma unroll
                for (int j = 0; j < 4; j++) c[mt][nt][j] = 0.f;

#pragma unroll
        for (int kt = 0; kt < 2; kt++) {
            uint a[2][4];
#pragma unroll
            for (int mt = 0; mt < 2; mt++) {
                const __half* p = &sea_h[mt * 16 + gid][kt * 16 + tig * 2];
                a[mt][0] = *(const uint*)p;
                a[mt][1] = *(const uint*)(p + 8 * 40);
                a[mt][2] = *(const uint*)(p + 8);
                a[mt][3] = *(const uint*)(p + 8 * 40 + 8);
            }
#pragma unroll
            for (int mt = 0; mt < 2; mt++)
#pragma unroll
                for (int nt = 0; nt < 4; nt++)
                    mma16816(c[mt][nt], a[mt], b[nt][kt]);
        }

#pragma unroll
        for (int mt = 0; mt < 2; mt++) {
#pragma unroll
            for (int nt = 0; nt < 4; nt++) {
                int col = outbase + nt * 8 + tig * 2;
                *(float2*)&sE[mt * 16 + gid][col]     = make_float2(c[mt][nt][0], c[mt][nt][1]);
                *(float2*)&sE[mt * 16 + gid + 8][col] = make_float2(c[mt][nt][2], c[mt][nt][3]);
            }
        }
        __syncthreads();

        {
            int e0 = tid >> 3, k40 = (tid & 7) * 4;
            __half2 h0 = __floats2half2_rn(n0.x, n0.y);
            __half2 h1 = __floats2half2_rn(n0.z, n0.w);
            *(uint2*)&sea_h[e0][k40] = make_uint2(h2u(h0), h2u(h1));
            int i1 = tid + 128;
            int e1 = i1 >> 3, k41 = (i1 & 7) * 4;
            __half2 h2 = __floats2half2_rn(n1.x, n1.y);
            __half2 h3 = __floats2half2_rn(n1.z, n1.w);
            *(uint2*)&sea_h[e1][k41] = make_uint2(h2u(h2), h2u(h3));
            if (tid < 64) sidx[tid] = nidx;
        }

        // ---- apply: 16 lanes/edge, 4 ch/lane, uint4 gathers + red.v4 ----
        uint4 nd[4], ns[4];
#pragma unroll
        for (int t = 0; t < 4; t++) {
            nd[t] = __ldg((const uint4*)&d_nd[(ull)dsts[t] * 64 + 4 * q]);
            ns[t] = __ldg((const uint4*)&d_ns[(ull)srcs[t] * 64 + 4 * q]);
        }
#pragma unroll
        for (int t = 0; t < 4; t++) {
            int e = warp * 8 + t * 2 + half;
            // nd.x = Af(ch0,ch1), nd.y = As(ch0,ch1), nd.z = Af(ch2,ch3), nd.w = As(ch2,ch3)
            float2 af01 = __half22float2(*(__half2*)&nd[t].x);
            float2 as01 = __half22float2(*(__half2*)&nd[t].y);
            float2 af23 = __half22float2(*(__half2*)&nd[t].z);
            float2 as23 = __half22float2(*(__half2*)&nd[t].w);
            float2 bf01 = __half22float2(*(__half2*)&ns[t].x);
            float2 bs01 = __half22float2(*(__half2*)&ns[t].y);
            float2 bf23 = __half22float2(*(__half2*)&ns[t].z);
            float2 bs23 = __half22float2(*(__half2*)&ns[t].w);

            float4 Ef = *(const float4*)&sE[e][4 * q];
            float4 Es = *(const float4*)&sE[e][64 + 4 * q];

            float pf0 = Ef.x + af01.x + bf01.x;
            float pf1 = Ef.y + af01.y + bf01.y;
            float pf2 = Ef.z + af23.x + bf23.x;
            float pf3 = Ef.w + af23.y + bf23.y;
            float ps0 = Es.x + as01.x + bs01.x;
            float ps1 = Es.y + as01.y + bs01.y;
            float ps2 = Es.z + as23.x + bs23.x;
            float ps3 = Es.w + as23.y + bs23.y;

            float m0 = sigmoid_tanh_(pf0) * softplusf_(ps0);
            float m1 = sigmoid_tanh_(pf1) * softplusf_(ps1);
            float m2 = sigmoid_tanh_(pf2) * softplusf_(ps2);
            float m3 = sigmoid_tanh_(pf3) * softplusf_(ps3);

            float* dp = d_agg + (ull)dsts[t] * HID + 4 * q;
            asm volatile("red.global.add.v4.f32 [%0], {%1,%2,%3,%4};"
                         :: "l"(dp), "f"(m0), "f"(m1), "f"(m2), "f"(m3) : "memory");
        }
        __syncthreads();
    }
}

// float4-vectorized channel stats of d_agg -> d_sum1[layer]
__global__ void k_stats_agg(int layer) {
    int tid = threadIdx.x;
    float4 s = {0,0,0,0}, q = {0,0,0,0};
    int stride = gridDim.x * blockDim.x;
    const float4* a4 = (const float4*)d_agg;
    for (int i = blockIdx.x * blockDim.x + tid; i < NN * 16; i += stride) {
        float4 v = a4[i];
        s.x += v.x; s.y += v.y; s.z += v.z; s.w += v.w;
        q.x = fmaf(v.x, v.x, q.x); q.y = fmaf(v.y, v.y, q.y);
        q.z = fmaf(v.z, v.z, q.z); q.w = fmaf(v.w, v.w, q.w);
    }
    __shared__ float4 ss[256], sq[256];
    ss[tid] = s; sq[tid] = q;
    __syncthreads();
#pragma unroll
    for (int o = 128; o >= 16; o >>= 1) {
        if (tid < o) {
            ss[tid].x += ss[tid+o].x; ss[tid].y += ss[tid+o].y;
            ss[tid].z += ss[tid+o].z; ss[tid].w += ss[tid+o].w;
            sq[tid].x += sq[tid+o].x; sq[tid].y += sq[tid+o].y;
            sq[tid].z += sq[tid+o].z; sq[tid].w += sq[tid+o].w;
        }
        __syncthreads();
    }
    if (tid < 16) {
        atomicAdd(&d_sum1[layer][4*tid+0], (double)ss[tid].x);
        atomicAdd(&d_sum1[layer][4*tid+1], (double)ss[tid].y);
        atomicAdd(&d_sum1[layer][4*tid+2], (double)ss[tid].z);
        atomicAdd(&d_sum1[layer][4*tid+3], (double)ss[tid].w);
        atomicAdd(&d_sumsq1[layer][4*tid+0], (double)sq[tid].x);
        atomicAdd(&d_sumsq1[layer][4*tid+1], (double)sq[tid].y);
        atomicAdd(&d_sumsq1[layer][4*tid+2], (double)sq[tid].z);
        atomicAdd(&d_sumsq1[layer][4*tid+3], (double)sq[tid].w);
    }
}

// apply cbn + residual (float4), write x_new into d_agg, accumulate obn stats
__global__ void k_apply_cbn(const float* __restrict__ gc, const float* __restrict__ bc, int layer) {
    int tid = threadIdx.x;
    int g = tid & 15;
    float mn[4], rsg[4], bb[4];
#pragma unroll
    for (int j = 0; j < 4; j++) {
        int c = 4 * g + j;
        double mean = d_sum1[layer][c] * (1.0 / NN);
        double var  = d_sumsq1[layer][c] * (1.0 / NN) - mean * mean;
        float rs = (float)rsqrt(var + 1e-5);
        mn[j] = (float)mean; rsg[j] = rs * gc[c]; bb[j] = bc[c];
    }
    float4 s = {0,0,0,0}, q = {0,0,0,0};
    int stride = gridDim.x * blockDim.x;
    float4* a4 = (float4*)d_agg;
    const float4* x4 = (const float4*)d_x;
    for (int i = blockIdx.x * blockDim.x + tid; i < NN * 16; i += stride) {
        float4 a = a4[i];
        float4 x = x4[i];
        float4 xn;
        xn.x = (a.x - mn[0]) * rsg[0] + bb[0] + x.x;
        xn.y = (a.y - mn[1]) * rsg[1] + bb[1] + x.y;
        xn.z = (a.z - mn[2]) * rsg[2] + bb[2] + x.z;
        xn.w = (a.w - mn[3]) * rsg[3] + bb[3] + x.w;
        a4[i] = xn;
        s.x += xn.x; s.y += xn.y; s.z += xn.z; s.w += xn.w;
        q.x = fmaf(xn.x, xn.x, q.x); q.y = fmaf(xn.y, xn.y, q.y);
        q.z = fmaf(xn.z, xn.z, q.z); q.w = fmaf(xn.w, xn.w, q.w);
    }
    __shared__ float4 ss[256], sq[256];
    ss[tid] = s; sq[tid] = q;
    __syncthreads();
#pragma unroll
    for (int o = 128; o >= 16; o >>= 1) {
        if (tid < o) {
            ss[tid].x += ss[tid+o].x; ss[tid].y += ss[tid+o].y;
            ss[tid].z += ss[tid+o].z; ss[tid].w += ss[tid+o].w;
            sq[tid].x += sq[tid+o].x; sq[tid].y += sq[tid+o].y;
            sq[tid].z += sq[tid+o].z; sq[tid].w += sq[tid+o].w;
        }
        __syncthreads();
    }
    if (tid < 16) {
        atomicAdd(&d_sum2[layer][4*tid+0], (double)ss[tid].x);
        atomicAdd(&d_sum2[layer][4*tid+1], (double)ss[tid].y);
        atomicAdd(&d_sum2[layer][4*tid+2], (double)ss[tid].z);
        atomicAdd(&d_sum2[layer][4*tid+3], (double)ss[tid].w);
        atomicAdd(&d_sumsq2[layer][4*tid+0], (double)sq[tid].x);
        atomicAdd(&d_sumsq2[layer][4*tid+1], (double)sq[tid].y);
        atomicAdd(&d_sumsq2[layer][4*tid+2], (double)sq[tid].z);
        atomicAdd(&d_sumsq2[layer][4*tid+3], (double)sq[tid].w);
    }
}

// final obn + softplus -> d_x (last layer only)
__global__ void k_final_obn(const float* __restrict__ go, const float* __restrict__ bo, int layer) {
    int tid = threadIdx.x;
    int g = tid & 15;
    float mn[4], rsg[4], bb[4];
#pragma unroll
    for (int j = 0; j < 4; j++) {
        int c = 4 * g + j;
        double mean = d_sum2[layer][c] * (1.0 / NN);
        double var  = d_sumsq2[layer][c] * (1.0 / NN) - mean * mean;
        float rs = (float)rsqrt(var + 1e-5);
        mn[j] = (float)mean; rsg[j] = rs * go[c]; bb[j] = bo[c];
    }
    int stride = gridDim.x * blockDim.x;
    const float4* a4 = (const float4*)d_agg;
    float4* x4 = (float4*)d_x;
    for (int i = blockIdx.x * blockDim.x + tid; i < NN * 16; i += stride) {
        float4 a = a4[i];
        float4 r;
        r.x = softplusf_((a.x - mn[0]) * rsg[0] + bb[0]);
        r.y = softplusf_((a.y - mn[1]) * rsg[1] + bb[1]);
        r.z = softplusf_((a.z - mn[2]) * rsg[2] + bb[2]);
        r.w = softplusf_((a.w - mn[3]) * rsg[3] + bb[3]);
        x4[i] = r;
    }
}

__global__ void k_pool(const int* __restrict__ batch) {
    int i = blockIdx.x * blockDim.x + threadIdx.x;
    if (i < NN * 16) {
        int n = i >> 4, q = i & 15;
        int g = batch[n];
        float4 v = *(const float4*)(d_x + n * HID + 4 * q);
        float* p = d_pool + g * HID + 4 * q;
        asm volatile("red.global.add.v4.f32 [%0], {%1,%2,%3,%4};"
                     :: "l"(p), "f"(v.x), "f"(v.y), "f"(v.z), "f"(v.w) : "memory");
    }
}

__global__ void k_cnt(const int* __restrict__ batch) {
    int n = blockIdx.x * blockDim.x + threadIdx.x;
    if (n < NN) atomicAdd(&d_cnt[batch[n]], 1.0f);
}

__global__ void k_head(const float* __restrict__ W1, const float* __restrict__ b1,
                       const float* __restrict__ W2, const float* __restrict__ b2,
                       float* __restrict__ out)
{
    int g = blockIdx.x;
    int t = threadIdx.x;
    __shared__ float sp[64];
    __shared__ float sh[64];
    float cnt = fmaxf(d_cnt[g], 1.0f);
    sp[t] = d_pool[g * HID + t] / cnt;
    __syncthreads();
    float acc = b1[t];
#pragma unroll
    for (int k = 0; k < 64; k++)
        acc = fmaf(sp[k], W1[k * HID + t], acc);
    float h = acc * sigmoidf_(acc);
    sh[t] = h * W2[t];
    __syncthreads();
    if (t < 32) {
        float v = sh[t] + sh[t + 32];
#pragma unroll
        for (int o = 16; o > 0; o >>= 1)
            v += __shfl_down_sync(0xffffffffu, v, o);
        if (t == 0) out[g] = v + b2[0];
    }
}

// ---------------- launch ----------------
extern "C" void kernel_launch(void* const* d_in, const int* in_sizes, int n_in,
                              void* d_out, int out_size) {
    const int*   z     = (const int*)  d_in[0];
    const int*   ei    = (const int*)  d_in[1];
    const float* ea    = (const float*)d_in[2];
    const int*   batch = (const int*)  d_in[3];
    const float* emb   = (const float*)d_in[4];
    const float* Wf    = (const float*)d_in[5];
    const float* bf    = (const float*)d_in[6];
    const float* Ws    = (const float*)d_in[7];
    const float* bs    = (const float*)d_in[8];
    const float* gc    = (const float*)d_in[9];
    const float* bc    = (const float*)d_in[10];
    const float* go    = (const float*)d_in[11];
    const float* bo    = (const float*)d_in[12];
    const float* W1    = (const float*)d_in[13];
    const float* b1    = (const float*)d_in[14];
    const float* W2    = (const float*)d_in[15];
    const float* b2    = (const float*)d_in[16];
    float* out = (float*)d_out;

    k_gather<<<(NN * HID + 255) / 256, 256>>>(z, emb);

    for (int l = 0; l < NLAYERS; l++) {
        const float* Wfl = Wf + l * ZW * HID;
        const float* Wsl = Ws + l * ZW * HID;
        k_node_pre<<<592, 256>>>(Wfl, bf + l * HID, Wsl, bs + l * HID,
                                 go + (l - 1) * HID, bo + (l - 1) * HID, l - 1);
        k_edge_fused<<<740, 128>>>(ei, ea, Wfl, Wsl);
        k_stats_agg<<<256, 256>>>(l);
        k_apply_cbn<<<256, 256>>>(gc + l * HID, bc + l * HID, l);
    }
    k_final_obn<<<256, 256>>>(go + 3 * HID, bo + 3 * HID, 3);

    k_zero_pool<<<(NG * HID + 255) / 256, 256>>>();
    k_pool<<<(NN * 16 + 255) / 256, 256>>>(batch);
    k_cnt<<<(NN + 255) / 256, 256>>>(batch);
    k_head<<<NG, 64>>>(W1, b1, W2, b2, out);
}

// round 12
// speedup vs baseline: 1.0573x; 1.0573x over previous
#include <cuda_runtime.h>
#include <cuda_fp16.h>

#define NN 100000
#define NE 1000000
#define NG 512
#define HID 64
#define EDIM 32
#define ZW 160
#define NLAYERS 4

typedef unsigned long long ull;
typedef unsigned int uint;

// ---------------- scratch ----------------
__device__ float d_x[NN * HID];
__device__ uint  d_nd[NN * 64];       // dst terms: half2(Af), half2(As) (bias incl.)
__device__ uint  d_ns[NN * 64];       // src terms: half2(Bf), half2(Bs)
__device__ float d_agg[NN * HID];
__device__ __half d_ea_h[NE * EDIM];  // fp16 edge_attr (pre-converted once)
__device__ double d_sum1[NLAYERS][64];
__device__ double d_sumsq1[NLAYERS][64];
__device__ double d_sum2[NLAYERS][64];
__device__ double d_sumsq2[NLAYERS][64];
__device__ float d_pool[NG * HID];
__device__ float d_cnt[NG];

// ---------------- helpers ----------------
__device__ __forceinline__ float sigmoidf_(float x) {
    return __fdividef(1.0f, 1.0f + __expf(-x));
}
__device__ __forceinline__ float sigmoid_tanh_(float x) {
    float t;
    asm("tanh.approx.f32 %0, %1;" : "=f"(t) : "f"(x * 0.5f));
    return fmaf(0.5f, t, 0.5f);
}
__device__ __forceinline__ float softplusf_(float x) {
    float e = __expf(-fabsf(x));
    return fmaxf(x, 0.0f) + __logf(1.0f + e);
}
__device__ __forceinline__ uint h2u(__half2 h) { return *(uint*)&h; }

// mma.sync m16n8k16 f16 inputs, f32 accumulate
__device__ __forceinline__ void mma16816(float c[4], const uint a[4], const uint b[2]) {
    asm volatile(
        "mma.sync.aligned.m16n8k16.row.col.f32.f16.f16.f32 "
        "{%0,%1,%2,%3}, {%4,%5,%6,%7}, {%8,%9}, {%0,%1,%2,%3};"
        : "+f"(c[0]), "+f"(c[1]), "+f"(c[2]), "+f"(c[3])
        : "r"(a[0]), "r"(a[1]), "r"(a[2]), "r"(a[3]), "r"(b[0]), "r"(b[1]));
}

// ---------------- kernels ----------------

__global__ void k_gather(const int* __restrict__ z, const float* __restrict__ emb) {
    int i = blockIdx.x * blockDim.x + threadIdx.x;
    if (i < NN * HID) {
        int n = i >> 6, c = i & 63;
        d_x[i] = emb[z[n] * HID + c];
        d_agg[i] = 0.f;
    }
    if (i < NLAYERS * 64) {
        int l = i >> 6, c = i & 63;
        d_sum1[l][c] = 0.0; d_sumsq1[l][c] = 0.0;
        d_sum2[l][c] = 0.0; d_sumsq2[l][c] = 0.0;
    }
}

// one-time: convert edge_attr fp32 -> fp16
__global__ void k_prep_ea(const float* __restrict__ ea) {
    int i = blockIdx.x * blockDim.x + threadIdx.x;
    if (i < NE * EDIM / 8) {
        const float4* s = (const float4*)ea;
        float4 v0 = __ldcs(s + 2 * i);
        float4 v1 = __ldcs(s + 2 * i + 1);
        uint4 o;
        o.x = h2u(__floats2half2_rn(v0.x, v0.y));
        o.y = h2u(__floats2half2_rn(v0.z, v0.w));
        o.z = h2u(__floats2half2_rn(v1.x, v1.y));
        o.w = h2u(__floats2half2_rn(v1.z, v1.w));
        ((uint4*)d_ea_h)[i] = o;
    }
}

// Tensor-core node pre-GEMM (round-10 version).
__global__ __launch_bounds__(256) void k_node_pre(
    const float* __restrict__ Wf, const float* __restrict__ bf,
    const float* __restrict__ Ws, const float* __restrict__ bs,
    const float* __restrict__ go, const float* __restrict__ bo,
    int prev_layer)
{
    __shared__ __half sxh[64][72];

    int tid = threadIdx.x;
    int warp = tid >> 5;
    int lane = tid & 31;
    int gid = lane >> 2;
    int tig = lane & 3;

    float mn[4], rsg[4], bb[4];
    if (prev_layer >= 0) {
        int q = tid & 15;
#pragma unroll
        for (int j = 0; j < 4; j++) {
            int c = 4 * q + j;
            double mean = d_sum2[prev_layer][c] * (1.0 / NN);
            double var  = d_sumsq2[prev_layer][c] * (1.0 / NN) - mean * mean;
            float rs = (float)rsqrt(var + 1e-5);
            mn[j] = (float)mean; rsg[j] = rs * go[c]; bb[j] = bo[c];
        }
    }

    int m = warp >> 1;
    int chb = (warp & 1) * 32;
    const float* Wsrc;
    const float* bias = nullptr;
    uint* outp;
    int slot;
    if (m == 0)      { Wsrc = Wf;            bias = bf; outp = d_nd; slot = 0; }
    else if (m == 1) { Wsrc = Wf + 64 * HID;            outp = d_ns; slot = 0; }
    else if (m == 2) { Wsrc = Ws;            bias = bs; outp = d_nd; slot = 1; }
    else             { Wsrc = Ws + 64 * HID;            outp = d_ns; slot = 1; }

    uint b[4][4][2];
#pragma unroll
    for (int nt = 0; nt < 4; nt++) {
#pragma unroll
        for (int kt = 0; kt < 4; kt++) {
            int ch = chb + nt * 8 + gid;
            int k0 = kt * 16 + tig * 2;
            b[nt][kt][0] = h2u(__floats2half2_rn(Wsrc[k0 * HID + ch],
                                                 Wsrc[(k0 + 1) * HID + ch]));
            b[nt][kt][1] = h2u(__floats2half2_rn(Wsrc[(k0 + 8) * HID + ch],
                                                 Wsrc[(k0 + 9) * HID + ch]));
        }
    }
    float bi[4][2];
#pragma unroll
    for (int nt = 0; nt < 4; nt++) {
        int ch = chb + nt * 8 + tig * 2;
        bi[nt][0] = bias ? bias[ch]     : 0.f;
        bi[nt][1] = bias ? bias[ch + 1] : 0.f;
    }

    for (int nb = blockIdx.x * 64; nb < NN; nb += gridDim.x * 64) {
        int nmax = NN - nb; if (nmax > 64) nmax = 64;

        {
            const float4* x4 = (const float4*)(d_x + (ull)nb * HID);
            float4* a4 = (float4*)(d_agg + (ull)nb * HID);
            float4* xw4 = (float4*)(d_x + (ull)nb * HID);
            for (int i = tid; i < nmax * 16; i += 256) {
                int n = i >> 4, q = i & 15;
                float4 v;
                if (prev_layer >= 0) {
                    float4 a = a4[i];
                    v.x = softplusf_((a.x - mn[0]) * rsg[0] + bb[0]);
                    v.y = softplusf_((a.y - mn[1]) * rsg[1] + bb[1]);
                    v.z = softplusf_((a.z - mn[2]) * rsg[2] + bb[2]);
                    v.w = softplusf_((a.w - mn[3]) * rsg[3] + bb[3]);
                    xw4[i] = v;
                    a4[i] = make_float4(0.f, 0.f, 0.f, 0.f);
                } else {
                    v = x4[i];
                }
                __half2 h0 = __floats2half2_rn(v.x, v.y);
                __half2 h1 = __floats2half2_rn(v.z, v.w);
                *(uint2*)&sxh[n][4 * q] = make_uint2(h2u(h0), h2u(h1));
            }
        }
        __syncthreads();

#pragma unroll
        for (int mt = 0; mt < 4; mt++) {
            float c[4][4];
#pragma unroll
            for (int nt = 0; nt < 4; nt++) {
                c[nt][0] = bi[nt][0]; c[nt][1] = bi[nt][1];
                c[nt][2] = bi[nt][0]; c[nt][3] = bi[nt][1];
            }
#pragma unroll
            for (int kt = 0; kt < 4; kt++) {
                uint a[4];
                const __half* p = &sxh[mt * 16 + gid][kt * 16 + tig * 2];
                a[0] = *(const uint*)p;
                a[1] = *(const uint*)(p + 8 * 72);
                a[2] = *(const uint*)(p + 8);
                a[3] = *(const uint*)(p + 8 * 72 + 8);
#pragma unroll
                for (int nt = 0; nt < 4; nt++)
                    mma16816(c[nt], a, b[nt][kt]);
            }
            int r0 = nb + mt * 16 + gid;
            int r1 = r0 + 8;
#pragma unroll
            for (int nt = 0; nt < 4; nt++) {
                int ch = chb + nt * 8 + tig * 2;
                if (r0 < NN) outp[(ull)r0 * 64 + ch + slot] = h2u(__floats2half2_rn(c[nt][0], c[nt][1]));
                if (r1 < NN) outp[(ull)r1 * 64 + ch + slot] = h2u(__floats2half2_rn(c[nt][2], c[nt][3]));
            }
        }
        __syncthreads();
    }
}

__global__ void k_zero_pool() {
    int i = blockIdx.x * blockDim.x + threadIdx.x;
    if (i < NG * HID) d_pool[i] = 0.f;
    if (i < NG) d_cnt[i] = 0.f;
}

// Fused edge kernel: HMMA GEMM (sequential m-tiles, low regs) + R10 apply.
// 5 blocks/SM target for latency hiding.
__global__ __launch_bounds__(128, 5) void k_edge_fused(
    const int* __restrict__ ei,
    const float* __restrict__ Wf, const float* __restrict__ Ws)
{
    __shared__ __half sea_h[32][40];
    __shared__ float sE[32][132];
    __shared__ int sidx[64];

    int tid = threadIdx.x;
    int warp = tid >> 5;
    int lane = tid & 31;
    int gid = lane >> 2;
    int tig = lane & 3;

    const float* W = (warp >> 1) ? Ws : Wf;
    int chb = (warp & 1) * 32;
    int outbase = (warp >> 1) * 64 + chb;

    uint b[4][2][2];
#pragma unroll
    for (int nt = 0; nt < 4; nt++) {
#pragma unroll
        for (int kt = 0; kt < 2; kt++) {
            int ch = chb + nt * 8 + gid;
            int k0 = kt * 16 + tig * 2;
            b[nt][kt][0] = h2u(__floats2half2_rn(W[(128 + k0)     * HID + ch],
                                                 W[(128 + k0 + 1) * HID + ch]));
            b[nt][kt][1] = h2u(__floats2half2_rn(W[(128 + k0 + 8) * HID + ch],
                                                 W[(128 + k0 + 9) * HID + ch]));
        }
    }

    const int stride = gridDim.x * 32;
    int base = blockIdx.x * 32;

    // prologue: load tile 'base' (fp16 source, 1 uint4 per thread)
    if (base < NE) {
        if (tid < 32)      sidx[tid] = ei[base + tid];
        else if (tid < 64) sidx[tid] = ei[NE + base + tid - 32];
        uint4 t = __ldcs(((const uint4*)(d_ea_h + (ull)base * EDIM)) + tid);
        int e = tid >> 2, seg = tid & 3;
        *(uint4*)&sea_h[e][seg * 8] = t;
    }
    __syncthreads();

    for (; base < NE; base += stride) {
        int nb = base + stride;
        int lb = (nb < NE) ? nb : 0;

        int srcs[8], dsts[8];
#pragma unroll
        for (int t = 0; t < 8; t++) {
            srcs[t] = sidx[warp * 8 + t];
            dsts[t] = sidx[32 + warp * 8 + t];
        }

        // prefetch next tile (fp16, 1 uint4 per thread) — overlaps GEMM
        uint4 nv = __ldcs(((const uint4*)(d_ea_h + (ull)lb * EDIM)) + tid);
        int nidx = 0;
        if (tid < 32)      nidx = ei[lb + tid];
        else if (tid < 64) nidx = ei[NE + lb + tid - 32];

        // ---- GEMM: sequential m-tiles (low live-register count) ----
#pragma unroll
        for (int mt = 0; mt < 2; mt++) {
            float c[4][4];
#pragma unroll
            for (int nt = 0; nt < 4; nt++)
#pragma unroll
                for (int j = 0; j < 4; j++) c[nt][j] = 0.f;
#pragma unroll
            for (int kt = 0; kt < 2; kt++) {
                uint a[4];
                const __half* p = &sea_h[mt * 16 + gid][kt * 16 + tig * 2];
                a[0] = *(const uint*)p;
                a[1] = *(const uint*)(p + 8 * 40);
                a[2] = *(const uint*)(p + 8);
                a[3] = *(const uint*)(p + 8 * 40 + 8);
#pragma unroll
                for (int nt = 0; nt < 4; nt++)
                    mma16816(c[nt], a, b[nt][kt]);
            }
#pragma unroll
            for (int nt = 0; nt < 4; nt++) {
                int col = outbase + nt * 8 + tig * 2;
                *(float2*)&sE[mt * 16 + gid][col]     = make_float2(c[nt][0], c[nt][1]);
                *(float2*)&sE[mt * 16 + gid + 8][col] = make_float2(c[nt][2], c[nt][3]);
            }
        }
        __syncthreads();   // sE ready; sea_h/sidx free

        // store next tile into sea_h/sidx
        {
            int e = tid >> 2, seg = tid & 3;
            *(uint4*)&sea_h[e][seg * 8] = nv;
            if (tid < 64) sidx[tid] = nidx;
        }

        // ---- apply: two batches of 4 edges (bounded live regs) ----
#pragma unroll
        for (int g2 = 0; g2 < 2; g2++) {
            uint2 nd[4], ns[4];
#pragma unroll
            for (int t = 0; t < 4; t++) {
                int idx = g2 * 4 + t;
                nd[t] = __ldg((const uint2*)&d_nd[(ull)dsts[idx] * 64 + 2 * lane]);
                ns[t] = __ldg((const uint2*)&d_ns[(ull)srcs[idx] * 64 + 2 * lane]);
            }
#pragma unroll
            for (int t = 0; t < 4; t++) {
                int idx = g2 * 4 + t;
                int e = warp * 8 + idx;
                float2 afv = __half22float2(*(__half2*)&nd[t].x);
                float2 asv = __half22float2(*(__half2*)&nd[t].y);
                float2 bfv = __half22float2(*(__half2*)&ns[t].x);
                float2 bsv = __half22float2(*(__half2*)&ns[t].y);

                float2 Ef = *(const float2*)&sE[e][2 * lane];
                float2 Es = *(const float2*)&sE[e][64 + 2 * lane];

                float pf0 = Ef.x + afv.x + bfv.x;
                float pf1 = Ef.y + afv.y + bfv.y;
                float ps0 = Es.x + asv.x + bsv.x;
                float ps1 = Es.y + asv.y + bsv.y;

                float m0 = sigmoid_tanh_(pf0) * softplusf_(ps0);
                float m1 = sigmoid_tanh_(pf1) * softplusf_(ps1);

                float* dp = d_agg + (ull)dsts[idx] * HID + 2 * lane;
                asm volatile("red.global.add.v2.f32 [%0], {%1,%2};"
                             :: "l"(dp), "f"(m0), "f"(m1) : "memory");
            }
        }
        __syncthreads();
    }
}

// float4-vectorized channel stats of d_agg -> d_sum1[layer]
__global__ void k_stats_agg(int layer) {
    int tid = threadIdx.x;
    float4 s = {0,0,0,0}, q = {0,0,0,0};
    int stride = gridDim.x * blockDim.x;
    const float4* a4 = (const float4*)d_agg;
    for (int i = blockIdx.x * blockDim.x + tid; i < NN * 16; i += stride) {
        float4 v = a4[i];
        s.x += v.x; s.y += v.y; s.z += v.z; s.w += v.w;
        q.x = fmaf(v.x, v.x, q.x); q.y = fmaf(v.y, v.y, q.y);
        q.z = fmaf(v.z, v.z, q.z); q.w = fmaf(v.w, v.w, q.w);
    }
    __shared__ float4 ss[256], sq[256];
    ss[tid] = s; sq[tid] = q;
    __syncthreads();
#pragma unroll
    for (int o = 128; o >= 16; o >>= 1) {
        if (tid < o) {
            ss[tid].x += ss[tid+o].x; ss[tid].y += ss[tid+o].y;
            ss[tid].z += ss[tid+o].z; ss[tid].w += ss[tid+o].w;
            sq[tid].x += sq[tid+o].x; sq[tid].y += sq[tid+o].y;
            sq[tid].z += sq[tid+o].z; sq[tid].w += sq[tid+o].w;
        }
        __syncthreads();
    }
    if (tid < 16) {
        atomicAdd(&d_sum1[layer][4*tid+0], (double)ss[tid].x);
        atomicAdd(&d_sum1[layer][4*tid+1], (double)ss[tid].y);
        atomicAdd(&d_sum1[layer][4*tid+2], (double)ss[tid].z);
        atomicAdd(&d_sum1[layer][4*tid+3], (double)ss[tid].w);
        atomicAdd(&d_sumsq1[layer][4*tid+0], (double)sq[tid].x);
        atomicAdd(&d_sumsq1[layer][4*tid+1], (double)sq[tid].y);
        atomicAdd(&d_sumsq1[layer][4*tid+2], (double)sq[tid].z);
        atomicAdd(&d_sumsq1[layer][4*tid+3], (double)sq[tid].w);
    }
}

// apply cbn + residual (float4), write x_new into d_agg, accumulate obn stats
__global__ void k_apply_cbn(const float* __restrict__ gc, const float* __restrict__ bc, int layer) {
    int tid = threadIdx.x;
    int g = tid & 15;
    float mn[4], rsg[4], bb[4];
#pragma unroll
    for (int j = 0; j < 4; j++) {
        int c = 4 * g + j;
        double mean = d_sum1[layer][c] * (1.0 / NN);
        double var  = d_sumsq1[layer][c] * (1.0 / NN) - mean * mean;
        float rs = (float)rsqrt(var + 1e-5);
        mn[j] = (float)mean; rsg[j] = rs * gc[c]; bb[j] = bc[c];
    }
    float4 s = {0,0,0,0}, q = {0,0,0,0};
    int stride = gridDim.x * blockDim.x;
    float4* a4 = (float4*)d_agg;
    const float4* x4 = (const float4*)d_x;
    for (int i = blockIdx.x * blockDim.x + tid; i < NN * 16; i += stride) {
        float4 a = a4[i];
        float4 x = x4[i];
        float4 xn;
        xn.x = (a.x - mn[0]) * rsg[0] + bb[0] + x.x;
        xn.y = (a.y - mn[1]) * rsg[1] + bb[1] + x.y;
        xn.z = (a.z - mn[2]) * rsg[2] + bb[2] + x.z;
        xn.w = (a.w - mn[3]) * rsg[3] + bb[3] + x.w;
        a4[i] = xn;
        s.x += xn.x; s.y += xn.y; s.z += xn.z; s.w += xn.w;
        q.x = fmaf(xn.x, xn.x, q.x); q.y = fmaf(xn.y, xn.y, q.y);
        q.z = fmaf(xn.z, xn.z, q.z); q.w = fmaf(xn.w, xn.w, q.w);
    }
    __shared__ float4 ss[256], sq[256];
    ss[tid] = s; sq[tid] = q;
    __syncthreads();
#pragma unroll
    for (int o = 128; o >= 16; o >>= 1) {
        if (tid < o) {
            ss[tid].x += ss[tid+o].x; ss[tid].y += ss[tid+o].y;
            ss[tid].z += ss[tid+o].z; ss[tid].w += ss[tid+o].w;
            sq[tid].x += sq[tid+o].x; sq[tid].y += sq[tid+o].y;
            sq[tid].z += sq[tid+o].z; sq[tid].w += sq[tid+o].w;
        }
        __syncthreads();
    }
    if (tid < 16) {
        atomicAdd(&d_sum2[layer][4*tid+0], (double)ss[tid].x);
        atomicAdd(&d_sum2[layer][4*tid+1], (double)ss[tid].y);
        atomicAdd(&d_sum2[layer][4*tid+2], (double)ss[tid].z);
        atomicAdd(&d_sum2[layer][4*tid+3], (double)ss[tid].w);
        atomicAdd(&d_sumsq2[layer][4*tid+0], (double)sq[tid].x);
        atomicAdd(&d_sumsq2[layer][4*tid+1], (double)sq[tid].y);
        atomicAdd(&d_sumsq2[layer][4*tid+2], (double)sq[tid].z);
        atomicAdd(&d_sumsq2[layer][4*tid+3], (double)sq[tid].w);
    }
}

// final obn + softplus -> d_x (last layer only)
__global__ void k_final_obn(const float* __restrict__ go, const float* __restrict__ bo, int layer) {
    int tid = threadIdx.x;
    int g = tid & 15;
    float mn[4], rsg[4], bb[4];
#pragma unroll
    for (int j = 0; j < 4; j++) {
        int c = 4 * g + j;
        double mean = d_sum2[layer][c] * (1.0 / NN);
        double var  = d_sumsq2[layer][c] * (1.0 / NN) - mean * mean;
        float rs = (float)rsqrt(var + 1e-5);
        mn[j] = (float)mean; rsg[j] = rs * go[c]; bb[j] = bo[c];
    }
    int stride = gridDim.x * blockDim.x;
    const float4* a4 = (const float4*)d_agg;
    float4* x4 = (float4*)d_x;
    for (int i = blockIdx.x * blockDim.x + tid; i < NN * 16; i += stride) {
        float4 a = a4[i];
        float4 r;
        r.x = softplusf_((a.x - mn[0]) * rsg[0] + bb[0]);
        r.y = softplusf_((a.y - mn[1]) * rsg[1] + bb[1]);
        r.z = softplusf_((a.z - mn[2]) * rsg[2] + bb[2]);
        r.w = softplusf_((a.w - mn[3]) * rsg[3] + bb[3]);
        x4[i] = r;
    }
}

__global__ void k_pool(const int* __restrict__ batch) {
    int i = blockIdx.x * blockDim.x + threadIdx.x;
    if (i < NN * 16) {
        int n = i >> 4, q = i & 15;
        int g = batch[n];
        float4 v = *(const float4*)(d_x + n * HID + 4 * q);
        float* p = d_pool + g * HID + 4 * q;
        asm volatile("red.global.add.v4.f32 [%0], {%1,%2,%3,%4};"
                     :: "l"(p), "f"(v.x), "f"(v.y), "f"(v.z), "f"(v.w) : "memory");
    }
}

__global__ void k_cnt(const int* __restrict__ batch) {
    int n = blockIdx.x * blockDim.x + threadIdx.x;
    if (n < NN) atomicAdd(&d_cnt[batch[n]], 1.0f);
}

__global__ void k_head(const float* __restrict__ W1, const float* __restrict__ b1,
                       const float* __restrict__ W2, const float* __restrict__ b2,
                       float* __restrict__ out)
{
    int g = blockIdx.x;
    int t = threadIdx.x;
    __shared__ float sp[64];
    __shared__ float sh[64];
    float cnt = fmaxf(d_cnt[g], 1.0f);
    sp[t] = d_pool[g * HID + t] / cnt;
    __syncthreads();
    float acc = b1[t];
#pragma unroll
    for (int k = 0; k < 64; k++)
        acc = fmaf(sp[k], W1[k * HID + t], acc);
    float h = acc * sigmoidf_(acc);
    sh[t] = h * W2[t];
    __syncthreads();
    if (t < 32) {
        float v = sh[t] + sh[t + 32];
#pragma unroll
        for (int o = 16; o > 0; o >>= 1)
            v += __shfl_down_sync(0xffffffffu, v, o);
        if (t == 0) out[g] = v + b2[0];
    }
}

// ---------------- launch ----------------
extern "C" void kernel_launch(void* const* d_in, const int* in_sizes, int n_in,
                              void* d_out, int out_size) {
    const int*   z     = (const int*)  d_in[0];
    const int*   ei    = (const int*)  d_in[1];
    const float* ea    = (const float*)d_in[2];
    const int*   batch = (const int*)  d_in[3];
    const float* emb   = (const float*)d_in[4];
    const float* Wf    = (const float*)d_in[5];
    const float* bf    = (const float*)d_in[6];
    const float* Ws    = (const float*)d_in[7];
    const float* bs    = (const float*)d_in[8];
    const float* gc    = (const float*)d_in[9];
    const float* bc    = (const float*)d_in[10];
    const float* go    = (const float*)d_in[11];
    const float* bo    = (const float*)d_in[12];
    const float* W1    = (const float*)d_in[13];
    const float* b1    = (const float*)d_in[14];
    const float* W2    = (const float*)d_in[15];
    const float* b2    = (const float*)d_in[16];
    float* out = (float*)d_out;

    k_gather<<<(NN * HID + 255) / 256, 256>>>(z, emb);
    k_prep_ea<<<(NE * EDIM / 8 + 255) / 256, 256>>>(ea);

    for (int l = 0; l < NLAYERS; l++) {
        const float* Wfl = Wf + l * ZW * HID;
        const float* Wsl = Ws + l * ZW * HID;
        k_node_pre<<<592, 256>>>(Wfl, bf + l * HID, Wsl, bs + l * HID,
                                 go + (l - 1) * HID, bo + (l - 1) * HID, l - 1);
        k_edge_fused<<<740, 128>>>(ei, Wfl, Wsl);
        k_stats_agg<<<256, 256>>>(l);
        k_apply_cbn<<<256, 256>>>(gc + l * HID, bc + l * HID, l);
    }
    k_final_obn<<<256, 256>>>(go + 3 * HID, bo + 3 * HID, 3);

    k_zero_pool<<<(NG * HID + 255) / 256, 256>>>();
    k_pool<<<(NN * 16 + 255) / 256, 256>>>(batch);
    k_cnt<<<(NN + 255) / 256, 256>>>(batch);
    k_head<<<NG, 64>>>(W1, b1, W2, b2, out);
}

// round 13
// speedup vs baseline: 1.0923x; 1.0331x over previous
#include <cuda_runtime.h>
#include <cuda_fp16.h>

#define NN 100000
#define NE 1000000
#define NG 512
#define HID 64
#define EDIM 32
#define ZW 160
#define NLAYERS 4

typedef unsigned long long ull;
typedef unsigned int uint;

// ---------------- scratch ----------------
__device__ float d_x[NN * HID];
__device__ uint  d_nd[NN * 64];       // dst terms: half2(Af), half2(As) (bias incl.)
__device__ uint  d_ns[NN * 64];       // src terms: half2(Bf), half2(Bs)
__device__ float d_agg[NN * HID];
__device__ __half d_ea_h[NE * EDIM];  // fp16 edge_attr (pre-converted once)
__device__ double d_sum1[NLAYERS][64];
__device__ double d_sumsq1[NLAYERS][64];
__device__ double d_sum2[NLAYERS][64];
__device__ double d_sumsq2[NLAYERS][64];
__device__ float d_pool[NG * HID];
__device__ float d_cnt[NG];

// ---------------- helpers ----------------
__device__ __forceinline__ float sigmoidf_(float x) {
    return __fdividef(1.0f, 1.0f + __expf(-x));
}
__device__ __forceinline__ float sigmoid_tanh_(float x) {
    float t;
    asm("tanh.approx.f32 %0, %1;" : "=f"(t) : "f"(x * 0.5f));
    return fmaf(0.5f, t, 0.5f);
}
__device__ __forceinline__ float softplusf_(float x) {
    float e = __expf(-fabsf(x));
    return fmaxf(x, 0.0f) + __logf(1.0f + e);
}
__device__ __forceinline__ uint h2u(__half2 h) { return *(uint*)&h; }

// mma.sync m16n8k16 f16 inputs, f32 accumulate
__device__ __forceinline__ void mma16816(float c[4], const uint a[4], const uint b[2]) {
    asm volatile(
        "mma.sync.aligned.m16n8k16.row.col.f32.f16.f16.f32 "
        "{%0,%1,%2,%3}, {%4,%5,%6,%7}, {%8,%9}, {%0,%1,%2,%3};"
        : "+f"(c[0]), "+f"(c[1]), "+f"(c[2]), "+f"(c[3])
        : "r"(a[0]), "r"(a[1]), "r"(a[2]), "r"(a[3]), "r"(b[0]), "r"(b[1]));
}
// ldmatrix x4 (A fragments for m16n8k16)
__device__ __forceinline__ void ldsm4(uint a[4], const __half* p) {
    uint sa = (uint)__cvta_generic_to_shared(p);
    asm volatile("ldmatrix.sync.aligned.m8n8.x4.shared.b16 {%0,%1,%2,%3}, [%4];"
                 : "=r"(a[0]), "=r"(a[1]), "=r"(a[2]), "=r"(a[3]) : "r"(sa));
}

// ---------------- kernels ----------------

__global__ void k_gather(const int* __restrict__ z, const float* __restrict__ emb) {
    int i = blockIdx.x * blockDim.x + threadIdx.x;
    if (i < NN * HID) {
        int n = i >> 6, c = i & 63;
        d_x[i] = emb[z[n] * HID + c];
        d_agg[i] = 0.f;
    }
    if (i < NLAYERS * 64) {
        int l = i >> 6, c = i & 63;
        d_sum1[l][c] = 0.0; d_sumsq1[l][c] = 0.0;
        d_sum2[l][c] = 0.0; d_sumsq2[l][c] = 0.0;
    }
}

// one-time: convert edge_attr fp32 -> fp16
__global__ void k_prep_ea(const float* __restrict__ ea) {
    int i = blockIdx.x * blockDim.x + threadIdx.x;
    if (i < NE * EDIM / 8) {
        const float4* s = (const float4*)ea;
        float4 v0 = __ldcs(s + 2 * i);
        float4 v1 = __ldcs(s + 2 * i + 1);
        uint4 o;
        o.x = h2u(__floats2half2_rn(v0.x, v0.y));
        o.y = h2u(__floats2half2_rn(v0.z, v0.w));
        o.z = h2u(__floats2half2_rn(v1.x, v1.y));
        o.w = h2u(__floats2half2_rn(v1.z, v1.w));
        ((uint4*)d_ea_h)[i] = o;
    }
}

// Tensor-core node pre-GEMM (ldmatrix A-fragments).
__global__ __launch_bounds__(256) void k_node_pre(
    const float* __restrict__ Wf, const float* __restrict__ bf,
    const float* __restrict__ Ws, const float* __restrict__ bs,
    const float* __restrict__ go, const float* __restrict__ bo,
    int prev_layer)
{
    __shared__ __half sxh[64][72];

    int tid = threadIdx.x;
    int warp = tid >> 5;
    int lane = tid & 31;
    int gid = lane >> 2;
    int tig = lane & 3;

    float mn[4], rsg[4], bb[4];
    if (prev_layer >= 0) {
        int q = tid & 15;
#pragma unroll
        for (int j = 0; j < 4; j++) {
            int c = 4 * q + j;
            double mean = d_sum2[prev_layer][c] * (1.0 / NN);
            double var  = d_sumsq2[prev_layer][c] * (1.0 / NN) - mean * mean;
            float rs = (float)rsqrt(var + 1e-5);
            mn[j] = (float)mean; rsg[j] = rs * go[c]; bb[j] = bo[c];
        }
    }

    int m = warp >> 1;
    int chb = (warp & 1) * 32;
    const float* Wsrc;
    const float* bias = nullptr;
    uint* outp;
    int slot;
    if (m == 0)      { Wsrc = Wf;            bias = bf; outp = d_nd; slot = 0; }
    else if (m == 1) { Wsrc = Wf + 64 * HID;            outp = d_ns; slot = 0; }
    else if (m == 2) { Wsrc = Ws;            bias = bs; outp = d_nd; slot = 1; }
    else             { Wsrc = Ws + 64 * HID;            outp = d_ns; slot = 1; }

    uint b[4][4][2];
#pragma unroll
    for (int nt = 0; nt < 4; nt++) {
#pragma unroll
        for (int kt = 0; kt < 4; kt++) {
            int ch = chb + nt * 8 + gid;
            int k0 = kt * 16 + tig * 2;
            b[nt][kt][0] = h2u(__floats2half2_rn(Wsrc[k0 * HID + ch],
                                                 Wsrc[(k0 + 1) * HID + ch]));
            b[nt][kt][1] = h2u(__floats2half2_rn(Wsrc[(k0 + 8) * HID + ch],
                                                 Wsrc[(k0 + 9) * HID + ch]));
        }
    }
    float bi[4][2];
#pragma unroll
    for (int nt = 0; nt < 4; nt++) {
        int ch = chb + nt * 8 + tig * 2;
        bi[nt][0] = bias ? bias[ch]     : 0.f;
        bi[nt][1] = bias ? bias[ch + 1] : 0.f;
    }

    // ldmatrix source row/col for this lane
    int lrow = lane & 15;
    int lcol = (lane >> 4) * 8;

    for (int nb = blockIdx.x * 64; nb < NN; nb += gridDim.x * 64) {
        int nmax = NN - nb; if (nmax > 64) nmax = 64;

        {
            const float4* x4 = (const float4*)(d_x + (ull)nb * HID);
            float4* a4 = (float4*)(d_agg + (ull)nb * HID);
            float4* xw4 = (float4*)(d_x + (ull)nb * HID);
            for (int i = tid; i < nmax * 16; i += 256) {
                int n = i >> 4, q = i & 15;
                float4 v;
                if (prev_layer >= 0) {
                    float4 a = a4[i];
                    v.x = softplusf_((a.x - mn[0]) * rsg[0] + bb[0]);
                    v.y = softplusf_((a.y - mn[1]) * rsg[1] + bb[1]);
                    v.z = softplusf_((a.z - mn[2]) * rsg[2] + bb[2]);
                    v.w = softplusf_((a.w - mn[3]) * rsg[3] + bb[3]);
                    xw4[i] = v;
                    a4[i] = make_float4(0.f, 0.f, 0.f, 0.f);
                } else {
                    v = x4[i];
                }
                __half2 h0 = __floats2half2_rn(v.x, v.y);
                __half2 h1 = __floats2half2_rn(v.z, v.w);
                *(uint2*)&sxh[n][4 * q] = make_uint2(h2u(h0), h2u(h1));
            }
        }
        __syncthreads();

#pragma unroll
        for (int mt = 0; mt < 4; mt++) {
            float c[4][4];
#pragma unroll
            for (int nt = 0; nt < 4; nt++) {
                c[nt][0] = bi[nt][0]; c[nt][1] = bi[nt][1];
                c[nt][2] = bi[nt][0]; c[nt][3] = bi[nt][1];
            }
#pragma unroll
            for (int kt = 0; kt < 4; kt++) {
                uint a[4];
                ldsm4(a, &sxh[mt * 16 + lrow][kt * 16 + lcol]);
#pragma unroll
                for (int nt = 0; nt < 4; nt++)
                    mma16816(c[nt], a, b[nt][kt]);
            }
            int r0 = nb + mt * 16 + gid;
            int r1 = r0 + 8;
#pragma unroll
            for (int nt = 0; nt < 4; nt++) {
                int ch = chb + nt * 8 + tig * 2;
                if (r0 < NN) outp[(ull)r0 * 64 + ch + slot] = h2u(__floats2half2_rn(c[nt][0], c[nt][1]));
                if (r1 < NN) outp[(ull)r1 * 64 + ch + slot] = h2u(__floats2half2_rn(c[nt][2], c[nt][3]));
            }
        }
        __syncthreads();
    }
}

__global__ void k_zero_pool() {
    int i = blockIdx.x * blockDim.x + threadIdx.x;
    if (i < NG * HID) d_pool[i] = 0.f;
    if (i < NG) d_cnt[i] = 0.f;
}

// Fused edge kernel: HMMA GEMM (ldmatrix A) + fp16 sE + apply.
__global__ __launch_bounds__(128, 5) void k_edge_fused(
    const int* __restrict__ ei,
    const float* __restrict__ Wf, const float* __restrict__ Ws)
{
    __shared__ __half sea_h[32][40];
    __shared__ uint sE[32][68];       // fp16 GEMM result: [e][col] col=half2 idx; f=0-31, s=32-63
    __shared__ int sidx[64];

    int tid = threadIdx.x;
    int warp = tid >> 5;
    int lane = tid & 31;
    int gid = lane >> 2;
    int tig = lane & 3;

    const float* W = (warp >> 1) ? Ws : Wf;
    int chb = (warp & 1) * 32;
    int outb2 = (warp >> 1) * 32 + (warp & 1) * 16;   // half2-col base

    uint b[4][2][2];
#pragma unroll
    for (int nt = 0; nt < 4; nt++) {
#pragma unroll
        for (int kt = 0; kt < 2; kt++) {
            int ch = chb + nt * 8 + gid;
            int k0 = kt * 16 + tig * 2;
            b[nt][kt][0] = h2u(__floats2half2_rn(W[(128 + k0)     * HID + ch],
                                                 W[(128 + k0 + 1) * HID + ch]));
            b[nt][kt][1] = h2u(__floats2half2_rn(W[(128 + k0 + 8) * HID + ch],
                                                 W[(128 + k0 + 9) * HID + ch]));
        }
    }

    int lrow = lane & 15;
    int lcol = (lane >> 4) * 8;

    const int stride = gridDim.x * 32;
    int base = blockIdx.x * 32;

    if (base < NE) {
        if (tid < 32)      sidx[tid] = ei[base + tid];
        else if (tid < 64) sidx[tid] = ei[NE + base + tid - 32];
        uint4 t = __ldcs(((const uint4*)(d_ea_h + (ull)base * EDIM)) + tid);
        int e = tid >> 2, seg = tid & 3;
        *(uint4*)&sea_h[e][seg * 8] = t;
    }
    __syncthreads();

    for (; base < NE; base += stride) {
        int nb = base + stride;
        int lb = (nb < NE) ? nb : 0;

        int srcs[8], dsts[8];
#pragma unroll
        for (int t = 0; t < 8; t++) {
            srcs[t] = sidx[warp * 8 + t];
            dsts[t] = sidx[32 + warp * 8 + t];
        }

        uint4 nv = __ldcs(((const uint4*)(d_ea_h + (ull)lb * EDIM)) + tid);
        int nidx = 0;
        if (tid < 32)      nidx = ei[lb + tid];
        else if (tid < 64) nidx = ei[NE + lb + tid - 32];

        // ---- GEMM: sequential m-tiles, ldmatrix A ----
#pragma unroll
        for (int mt = 0; mt < 2; mt++) {
            float c[4][4];
#pragma unroll
            for (int nt = 0; nt < 4; nt++)
#pragma unroll
                for (int j = 0; j < 4; j++) c[nt][j] = 0.f;
#pragma unroll
            for (int kt = 0; kt < 2; kt++) {
                uint a[4];
                ldsm4(a, &sea_h[mt * 16 + lrow][kt * 16 + lcol]);
#pragma unroll
                for (int nt = 0; nt < 4; nt++)
                    mma16816(c[nt], a, b[nt][kt]);
            }
#pragma unroll
            for (int nt = 0; nt < 4; nt++) {
                int col = outb2 + nt * 4 + tig;
                sE[mt * 16 + gid][col]     = h2u(__floats2half2_rn(c[nt][0], c[nt][1]));
                sE[mt * 16 + gid + 8][col] = h2u(__floats2half2_rn(c[nt][2], c[nt][3]));
            }
        }
        __syncthreads();   // sE ready; sea_h/sidx free

        {
            int e = tid >> 2, seg = tid & 3;
            *(uint4*)&sea_h[e][seg * 8] = nv;
            if (tid < 64) sidx[tid] = nidx;
        }

        // ---- apply: two batches of 4 edges ----
#pragma unroll
        for (int g2 = 0; g2 < 2; g2++) {
            uint2 nd[4], ns[4];
#pragma unroll
            for (int t = 0; t < 4; t++) {
                int idx = g2 * 4 + t;
                nd[t] = __ldg((const uint2*)&d_nd[(ull)dsts[idx] * 64 + 2 * lane]);
                ns[t] = __ldg((const uint2*)&d_ns[(ull)srcs[idx] * 64 + 2 * lane]);
            }
#pragma unroll
            for (int t = 0; t < 4; t++) {
                int idx = g2 * 4 + t;
                int e = warp * 8 + idx;
                float2 afv = __half22float2(*(__half2*)&nd[t].x);
                float2 asv = __half22float2(*(__half2*)&nd[t].y);
                float2 bfv = __half22float2(*(__half2*)&ns[t].x);
                float2 bsv = __half22float2(*(__half2*)&ns[t].y);

                float2 Ef = __half22float2(*(__half2*)&sE[e][lane]);
                float2 Es = __half22float2(*(__half2*)&sE[e][32 + lane]);

                float pf0 = Ef.x + afv.x + bfv.x;
                float pf1 = Ef.y + afv.y + bfv.y;
                float ps0 = Es.x + asv.x + bsv.x;
                float ps1 = Es.y + asv.y + bsv.y;

                float m0 = sigmoid_tanh_(pf0) * softplusf_(ps0);
                float m1 = sigmoid_tanh_(pf1) * softplusf_(ps1);

                float* dp = d_agg + (ull)dsts[idx] * HID + 2 * lane;
                asm volatile("red.global.add.v2.f32 [%0], {%1,%2};"
                             :: "l"(dp), "f"(m0), "f"(m1) : "memory");
            }
        }
        __syncthreads();
    }
}

// float4-vectorized channel stats of d_agg -> d_sum1[layer]
__global__ void k_stats_agg(int layer) {
    int tid = threadIdx.x;
    float4 s = {0,0,0,0}, q = {0,0,0,0};
    int stride = gridDim.x * blockDim.x;
    const float4* a4 = (const float4*)d_agg;
    for (int i = blockIdx.x * blockDim.x + tid; i < NN * 16; i += stride) {
        float4 v = a4[i];
        s.x += v.x; s.y += v.y; s.z += v.z; s.w += v.w;
        q.x = fmaf(v.x, v.x, q.x); q.y = fmaf(v.y, v.y, q.y);
        q.z = fmaf(v.z, v.z, q.z); q.w = fmaf(v.w, v.w, q.w);
    }
    __shared__ float4 ss[256], sq[256];
    ss[tid] = s; sq[tid] = q;
    __syncthreads();
#pragma unroll
    for (int o = 128; o >= 16; o >>= 1) {
        if (tid < o) {
            ss[tid].x += ss[tid+o].x; ss[tid].y += ss[tid+o].y;
            ss[tid].z += ss[tid+o].z; ss[tid].w += ss[tid+o].w;
            sq[tid].x += sq[tid+o].x; sq[tid].y += sq[tid+o].y;
            sq[tid].z += sq[tid+o].z; sq[tid].w += sq[tid+o].w;
        }
        __syncthreads();
    }
    if (tid < 16) {
        atomicAdd(&d_sum1[layer][4*tid+0], (double)ss[tid].x);
        atomicAdd(&d_sum1[layer][4*tid+1], (double)ss[tid].y);
        atomicAdd(&d_sum1[layer][4*tid+2], (double)ss[tid].z);
        atomicAdd(&d_sum1[layer][4*tid+3], (double)ss[tid].w);
        atomicAdd(&d_sumsq1[layer][4*tid+0], (double)sq[tid].x);
        atomicAdd(&d_sumsq1[layer][4*tid+1], (double)sq[tid].y);
        atomicAdd(&d_sumsq1[layer][4*tid+2], (double)sq[tid].z);
        atomicAdd(&d_sumsq1[layer][4*tid+3], (double)sq[tid].w);
    }
}

// apply cbn + residual (float4), write x_new into d_agg, accumulate obn stats
__global__ void k_apply_cbn(const float* __restrict__ gc, const float* __restrict__ bc, int layer) {
    int tid = threadIdx.x;
    int g = tid & 15;
    float mn[4], rsg[4], bb[4];
#pragma unroll
    for (int j = 0; j < 4; j++) {
        int c = 4 * g + j;
        double mean = d_sum1[layer][c] * (1.0 / NN);
        double var  = d_sumsq1[layer][c] * (1.0 / NN) - mean * mean;
        float rs = (float)rsqrt(var + 1e-5);
        mn[j] = (float)mean; rsg[j] = rs * gc[c]; bb[j] = bc[c];
    }
    float4 s = {0,0,0,0}, q = {0,0,0,0};
    int stride = gridDim.x * blockDim.x;
    float4* a4 = (float4*)d_agg;
    const float4* x4 = (const float4*)d_x;
    for (int i = blockIdx.x * blockDim.x + tid; i < NN * 16; i += stride) {
        float4 a = a4[i];
        float4 x = x4[i];
        float4 xn;
        xn.x = (a.x - mn[0]) * rsg[0] + bb[0] + x.x;
        xn.y = (a.y - mn[1]) * rsg[1] + bb[1] + x.y;
        xn.z = (a.z - mn[2]) * rsg[2] + bb[2] + x.z;
        xn.w = (a.w - mn[3]) * rsg[3] + bb[3] + x.w;
        a4[i] = xn;
        s.x += xn.x; s.y += xn.y; s.z += xn.z; s.w += xn.w;
        q.x = fmaf(xn.x, xn.x, q.x); q.y = fmaf(xn.y, xn.y, q.y);
        q.z = fmaf(xn.z, xn.z, q.z); q.w = fmaf(xn.w, xn.w, q.w);
    }
    __shared__ float4 ss[256], sq[256];
    ss[tid] = s; sq[tid] = q;
    __syncthreads();
#pragma unroll
    for (int o = 128; o >= 16; o >>= 1) {
        if (tid < o) {
            ss[tid].x += ss[tid+o].x; ss[tid].y += ss[tid+o].y;
            ss[tid].z += ss[tid+o].z; ss[tid].w += ss[tid+o].w;
            sq[tid].x += sq[tid+o].x; sq[tid].y += sq[tid+o].y;
            sq[tid].z += sq[tid+o].z; sq[tid].w += sq[tid+o].w;
        }
        __syncthreads();
    }
    if (tid < 16) {
        atomicAdd(&d_sum2[layer][4*tid+0], (double)ss[tid].x);
        atomicAdd(&d_sum2[layer][4*tid+1], (double)ss[tid].y);
        atomicAdd(&d_sum2[layer][4*tid+2], (double)ss[tid].z);
        atomicAdd(&d_sum2[layer][4*tid+3], (double)ss[tid].w);
        atomicAdd(&d_sumsq2[layer][4*tid+0], (double)sq[tid].x);
        atomicAdd(&d_sumsq2[layer][4*tid+1], (double)sq[tid].y);
        atomicAdd(&d_sumsq2[layer][4*tid+2], (double)sq[tid].z);
        atomicAdd(&d_sumsq2[layer][4*tid+3], (double)sq[tid].w);
    }
}

// final obn + softplus -> d_x (last layer only)
__global__ void k_final_obn(const float* __restrict__ go, const float* __restrict__ bo, int layer) {
    int tid = threadIdx.x;
    int g = tid & 15;
    float mn[4], rsg[4], bb[4];
#pragma unroll
    for (int j = 0; j < 4; j++) {
        int c = 4 * g + j;
        double mean = d_sum2[layer][c] * (1.0 / NN);
        double var  = d_sumsq2[layer][c] * (1.0 / NN) - mean * mean;
        float rs = (float)rsqrt(var + 1e-5);
        mn[j] = (float)mean; rsg[j] = rs * go[c]; bb[j] = bo[c];
    }
    int stride = gridDim.x * blockDim.x;
    const float4* a4 = (const float4*)d_agg;
    float4* x4 = (float4*)d_x;
    for (int i = blockIdx.x * blockDim.x + tid; i < NN * 16; i += stride) {
        float4 a = a4[i];
        float4 r;
        r.x = softplusf_((a.x - mn[0]) * rsg[0] + bb[0]);
        r.y = softplusf_((a.y - mn[1]) * rsg[1] + bb[1]);
        r.z = softplusf_((a.z - mn[2]) * rsg[2] + bb[2]);
        r.w = softplusf_((a.w - mn[3]) * rsg[3] + bb[3]);
        x4[i] = r;
    }
}

__global__ void k_pool(const int* __restrict__ batch) {
    int i = blockIdx.x * blockDim.x + threadIdx.x;
    if (i < NN * 16) {
        int n = i >> 4, q = i & 15;
        int g = batch[n];
        float4 v = *(const float4*)(d_x + n * HID + 4 * q);
        float* p = d_pool + g * HID + 4 * q;
        asm volatile("red.global.add.v4.f32 [%0], {%1,%2,%3,%4};"
                     :: "l"(p), "f"(v.x), "f"(v.y), "f"(v.z), "f"(v.w) : "memory");
    }
}

__global__ void k_cnt(const int* __restrict__ batch) {
    int n = blockIdx.x * blockDim.x + threadIdx.x;
    if (n < NN) atomicAdd(&d_cnt[batch[n]], 1.0f);
}

__global__ void k_head(const float* __restrict__ W1, const float* __restrict__ b1,
                       const float* __restrict__ W2, const float* __restrict__ b2,
                       float* __restrict__ out)
{
    int g = blockIdx.x;
    int t = threadIdx.x;
    __shared__ float sp[64];
    __shared__ float sh[64];
    float cnt = fmaxf(d_cnt[g], 1.0f);
    sp[t] = d_pool[g * HID + t] / cnt;
    __syncthreads();
    float acc = b1[t];
#pragma unroll
    for (int k = 0; k < 64; k++)
        acc = fmaf(sp[k], W1[k * HID + t], acc);
    float h = acc * sigmoidf_(acc);
    sh[t] = h * W2[t];
    __syncthreads();
    if (t < 32) {
        float v = sh[t] + sh[t + 32];
#pragma unroll
        for (int o = 16; o > 0; o >>= 1)
            v += __shfl_down_sync(0xffffffffu, v, o);
        if (t == 0) out[g] = v + b2[0];
    }
}

// ---------------- launch ----------------
extern "C" void kernel_launch(void* const* d_in, const int* in_sizes, int n_in,
                              void* d_out, int out_size) {
    const int*   z     = (const int*)  d_in[0];
    const int*   ei    = (const int*)  d_in[1];
    const float* ea    = (const float*)d_in[2];
    const int*   batch = (const int*)  d_in[3];
    const float* emb   = (const float*)d_in[4];
    const float* Wf    = (const float*)d_in[5];
    const float* bf    = (const float*)d_in[6];
    const float* Ws    = (const float*)d_in[7];
    const float* bs    = (const float*)d_in[8];
    const float* gc    = (const float*)d_in[9];
    const float* bc    = (const float*)d_in[10];
    const float* go    = (const float*)d_in[11];
    const float* bo    = (const float*)d_in[12];
    const float* W1    = (const float*)d_in[13];
    const float* b1    = (const float*)d_in[14];
    const float* W2    = (const float*)d_in[15];
    const float* b2    = (const float*)d_in[16];
    float* out = (float*)d_out;

    k_gather<<<(NN * HID + 255) / 256, 256>>>(z, emb);
    k_prep_ea<<<(NE * EDIM / 8 + 255) / 256, 256>>>(ea);

    for (int l = 0; l < NLAYERS; l++) {
        const float* Wfl = Wf + l * ZW * HID;
        const float* Wsl = Ws + l * ZW * HID;
        k_node_pre<<<592, 256>>>(Wfl, bf + l * HID, Wsl, bs + l * HID,
                                 go + (l - 1) * HID, bo + (l - 1) * HID, l - 1);
        k_edge_fused<<<740, 128>>>(ei, Wfl, Wsl);
        k_stats_agg<<<256, 256>>>(l);
        k_apply_cbn<<<256, 256>>>(gc + l * HID, bc + l * HID, l);
    }
    k_final_obn<<<256, 256>>>(go + 3 * HID, bo + 3 * HID, 3);

    k_zero_pool<<<(NG * HID + 255) / 256, 256>>>();
    k_pool<<<(NN * 16 + 255) / 256, 256>>>(batch);
    k_cnt<<<(NN + 255) / 256, 256>>>(batch);
    k_head<<<NG, 64>>>(W1, b1, W2, b2, out);
}